// round 1
// baseline (speedup 1.0000x reference)
#include <cuda_runtime.h>
#include <math.h>

#define D_MODEL 1024
#define NHEAD   16
#define HDIM    64
#define SEQ     2048
#define BATCH   2
#define MROWS   (BATCH*SEQ)      /* 4096 */
#define ATT_SCALE 0.125f         /* 1/sqrt(64) */
#define NTILE   (SEQ/64)         /* 32 */

/* Scratch (device globals: allocation is forbidden) */
__device__ float g_Q[BATCH*NHEAD*SEQ*HDIM];
__device__ float g_K[BATCH*NHEAD*SEQ*HDIM];
__device__ float g_V[BATCH*NHEAD*SEQ*HDIM];
__device__ float g_ctx[MROWS*D_MODEL];

/* ---------------- QKV projection: Y = X @ W^T + b, scatter to (B,H,S,Hd) ---- */
__global__ __launch_bounds__(256) void qkv_gemm(
    const float* __restrict__ X,
    const float* __restrict__ Wq, const float* __restrict__ Wk, const float* __restrict__ Wv,
    const float* __restrict__ bq, const float* __restrict__ bk, const float* __restrict__ bv)
{
    const float* W; const float* bias; float* Out;
    if (blockIdx.z == 0)      { W = Wq; bias = bq; Out = g_Q; }
    else if (blockIdx.z == 1) { W = Wk; bias = bk; Out = g_K; }
    else                      { W = Wv; bias = bv; Out = g_V; }

    __shared__ float As[16][128];   /* As[k][m] */
    __shared__ float Bs[16][128];   /* Bs[k][n] */

    const int tid = threadIdx.x;
    const int ty  = tid >> 4, tx = tid & 15;
    const int m0  = blockIdx.y * 128;
    const int n0  = blockIdx.x * 128;

    float acc[8][8];
    #pragma unroll
    for (int i = 0; i < 8; i++)
        #pragma unroll
        for (int j = 0; j < 8; j++) acc[i][j] = 0.f;

    for (int k0 = 0; k0 < 1024; k0 += 16) {
        __syncthreads();
        #pragma unroll
        for (int i = 0; i < 2; i++) {
            int f   = tid + i * 256;       /* 0..511 */
            int row = f >> 2;              /* 0..127 */
            int c4  = (f & 3) << 2;        /* 0,4,8,12 */
            float4 a = *(const float4*)(X + (size_t)(m0 + row) * 1024 + k0 + c4);
            As[c4+0][row] = a.x; As[c4+1][row] = a.y; As[c4+2][row] = a.z; As[c4+3][row] = a.w;
            float4 b = *(const float4*)(W + (size_t)(n0 + row) * 1024 + k0 + c4);
            Bs[c4+0][row] = b.x; Bs[c4+1][row] = b.y; Bs[c4+2][row] = b.z; Bs[c4+3][row] = b.w;
        }
        __syncthreads();
        #pragma unroll
        for (int kk = 0; kk < 16; kk++) {
            float4 a0 = *(const float4*)&As[kk][ty*4];
            float4 a1 = *(const float4*)&As[kk][64 + ty*4];
            float4 b0 = *(const float4*)&Bs[kk][tx*4];
            float4 b1 = *(const float4*)&Bs[kk][64 + tx*4];
            float av[8] = {a0.x,a0.y,a0.z,a0.w,a1.x,a1.y,a1.z,a1.w};
            float bw[8] = {b0.x,b0.y,b0.z,b0.w,b1.x,b1.y,b1.z,b1.w};
            #pragma unroll
            for (int i = 0; i < 8; i++)
                #pragma unroll
                for (int j = 0; j < 8; j++)
                    acc[i][j] = fmaf(av[i], bw[j], acc[i][j]);
        }
    }

    #pragma unroll
    for (int ib = 0; ib < 2; ib++) {
        #pragma unroll
        for (int i = 0; i < 4; i++) {
            int r  = m0 + ib*64 + ty*4 + i;
            int bb = r >> 11;          /* /2048 */
            int s  = r & 2047;
            #pragma unroll
            for (int jb = 0; jb < 2; jb++) {
                int c    = n0 + jb*64 + tx*4;
                int head = c >> 6;
                int hd   = c & 63;
                float4 v;
                v.x = acc[ib*4+i][jb*4+0] + bias[c+0];
                v.y = acc[ib*4+i][jb*4+1] + bias[c+1];
                v.z = acc[ib*4+i][jb*4+2] + bias[c+2];
                v.w = acc[ib*4+i][jb*4+3] + bias[c+3];
                *(float4*)(Out + ((size_t)(bb*NHEAD + head)*SEQ + s)*HDIM + hd) = v;
            }
        }
    }
}

/* ---------------- causal attention: two-pass exact softmax + ctx ------------ */
__global__ __launch_bounds__(256) void attn_kernel(float* __restrict__ attn)
{
    extern __shared__ float sm[];
    float (*Qs)[64] = (float(*)[64])(sm);           /* Qs[k][r] */
    float (*Ks)[64] = (float(*)[64])(sm + 4096);    /* Ks[k][c] */
    float (*Vs)[64] = (float(*)[64])(sm + 8192);    /* Vs[c][d] */
    float (*Ps)[68] = (float(*)[68])(sm + 12288);   /* Ps[c][r], pitch 68 */

    const int qt = blockIdx.x;           /* 0..31 q tile */
    const int bh = blockIdx.y;           /* 0..31 (b*16+h) */
    const int q0 = qt * 64;
    const float* Qp = g_Q + (size_t)bh * SEQ * HDIM;
    const float* Kp = g_K + (size_t)bh * SEQ * HDIM;
    const float* Vp = g_V + (size_t)bh * SEQ * HDIM;
    float* attnP = attn + (size_t)bh * SEQ * SEQ;

    const int tid = threadIdx.x;
    const int ty  = tid >> 4, tx = tid & 15;

    /* load Q tile transposed: Qs[k][r] */
    #pragma unroll
    for (int i = 0; i < 4; i++) {
        int f   = tid + i * 256;     /* 0..1023 */
        int row = f >> 4;            /* 0..63 */
        int c4  = (f & 15) << 2;
        float4 v = *(const float4*)(Qp + (size_t)(q0 + row) * HDIM + c4);
        Qs[c4+0][row] = v.x; Qs[c4+1][row] = v.y; Qs[c4+2][row] = v.z; Qs[c4+3][row] = v.w;
    }

    float m[4], l[4];
    #pragma unroll
    for (int i = 0; i < 4; i++) { m[i] = -INFINITY; l[i] = 0.f; }

    /* ---- pass 1: exact row max & sum (online) ---- */
    for (int kt = 0; kt <= qt; kt++) {
        __syncthreads();
        #pragma unroll
        for (int i = 0; i < 4; i++) {
            int f = tid + i * 256; int row = f >> 4; int c4 = (f & 15) << 2;
            float4 v = *(const float4*)(Kp + (size_t)(kt*64 + row) * HDIM + c4);
            Ks[c4+0][row] = v.x; Ks[c4+1][row] = v.y; Ks[c4+2][row] = v.z; Ks[c4+3][row] = v.w;
        }
        __syncthreads();

        float acc[4][4];
        #pragma unroll
        for (int i = 0; i < 4; i++)
            #pragma unroll
            for (int j = 0; j < 4; j++) acc[i][j] = 0.f;

        #pragma unroll 8
        for (int k = 0; k < 64; k++) {
            float4 qa = *(const float4*)&Qs[k][ty*4];
            float4 kb = *(const float4*)&Ks[k][tx*4];
            float qv[4] = {qa.x,qa.y,qa.z,qa.w};
            float kv[4] = {kb.x,kb.y,kb.z,kb.w};
            #pragma unroll
            for (int i = 0; i < 4; i++)
                #pragma unroll
                for (int j = 0; j < 4; j++)
                    acc[i][j] = fmaf(qv[i], kv[j], acc[i][j]);
        }

        const bool diag = (kt == qt);
        #pragma unroll
        for (int i = 0; i < 4; i++) {
            #pragma unroll
            for (int j = 0; j < 4; j++) {
                float s = acc[i][j] * ATT_SCALE;
                if (diag && (tx*4 + j > ty*4 + i)) s = -INFINITY;
                acc[i][j] = s;
            }
            float tmax = fmaxf(fmaxf(acc[i][0], acc[i][1]), fmaxf(acc[i][2], acc[i][3]));
            #pragma unroll
            for (int o = 8; o >= 1; o >>= 1)
                tmax = fmaxf(tmax, __shfl_xor_sync(0xffffffffu, tmax, o));
            float mn = fmaxf(m[i], tmax);
            float ssum = __expf(acc[i][0]-mn) + __expf(acc[i][1]-mn)
                       + __expf(acc[i][2]-mn) + __expf(acc[i][3]-mn);
            #pragma unroll
            for (int o = 8; o >= 1; o >>= 1)
                ssum += __shfl_xor_sync(0xffffffffu, ssum, o);
            l[i] = l[i] * __expf(m[i] - mn) + ssum;
            m[i] = mn;
        }
    }

    float linv[4];
    #pragma unroll
    for (int i = 0; i < 4; i++) linv[i] = 1.0f / l[i];

    /* ---- pass 2: write attn + accumulate ctx ---- */
    float cacc[4][4];
    #pragma unroll
    for (int i = 0; i < 4; i++)
        #pragma unroll
        for (int j = 0; j < 4; j++) cacc[i][j] = 0.f;

    for (int kt = 0; kt < NTILE; kt++) {
        if (kt <= qt) {
            __syncthreads();
            #pragma unroll
            for (int i = 0; i < 4; i++) {
                int f = tid + i * 256; int row = f >> 4; int c4 = (f & 15) << 2;
                float4 v = *(const float4*)(Kp + (size_t)(kt*64 + row) * HDIM + c4);
                Ks[c4+0][row] = v.x; Ks[c4+1][row] = v.y; Ks[c4+2][row] = v.z; Ks[c4+3][row] = v.w;
                float4 w = *(const float4*)(Vp + (size_t)(kt*64 + row) * HDIM + c4);
                *(float4*)&Vs[row][c4] = w;
            }
            __syncthreads();

            float acc[4][4];
            #pragma unroll
            for (int i = 0; i < 4; i++)
                #pragma unroll
                for (int j = 0; j < 4; j++) acc[i][j] = 0.f;

            #pragma unroll 8
            for (int k = 0; k < 64; k++) {
                float4 qa = *(const float4*)&Qs[k][ty*4];
                float4 kb = *(const float4*)&Ks[k][tx*4];
                float qv[4] = {qa.x,qa.y,qa.z,qa.w};
                float kv[4] = {kb.x,kb.y,kb.z,kb.w};
                #pragma unroll
                for (int i = 0; i < 4; i++)
                    #pragma unroll
                    for (int j = 0; j < 4; j++)
                        acc[i][j] = fmaf(qv[i], kv[j], acc[i][j]);
            }

            const bool diag = (kt == qt);
            float p[4][4];
            #pragma unroll
            for (int i = 0; i < 4; i++) {
                #pragma unroll
                for (int j = 0; j < 4; j++) {
                    float s = acc[i][j] * ATT_SCALE;
                    if (diag && (tx*4 + j > ty*4 + i)) s = -INFINITY;
                    p[i][j] = __expf(s - m[i]) * linv[i];
                }
                float4 v = make_float4(p[i][0], p[i][1], p[i][2], p[i][3]);
                *(float4*)(attnP + (size_t)(q0 + ty*4 + i) * SEQ + kt*64 + tx*4) = v;
            }
            #pragma unroll
            for (int i = 0; i < 4; i++)
                #pragma unroll
                for (int j = 0; j < 4; j++)
                    Ps[tx*4+j][ty*4+i] = p[i][j];
            __syncthreads();

            #pragma unroll 8
            for (int c = 0; c < 64; c++) {
                float4 pr = *(const float4*)&Ps[c][ty*4];
                float4 vv = *(const float4*)&Vs[c][tx*4];
                float pv[4] = {pr.x,pr.y,pr.z,pr.w};
                float vw[4] = {vv.x,vv.y,vv.z,vv.w};
                #pragma unroll
                for (int i = 0; i < 4; i++)
                    #pragma unroll
                    for (int j = 0; j < 4; j++)
                        cacc[i][j] = fmaf(pv[i], vw[j], cacc[i][j]);
            }
        } else {
            float4 z = make_float4(0.f, 0.f, 0.f, 0.f);
            #pragma unroll
            for (int i = 0; i < 4; i++)
                *(float4*)(attnP + (size_t)(q0 + ty*4 + i) * SEQ + kt*64 + tx*4) = z;
        }
    }

    /* ctx -> (B,S,D) row-major for the output projection */
    const int b = bh >> 4, h = bh & 15;
    #pragma unroll
    for (int i = 0; i < 4; i++) {
        float4 v = make_float4(cacc[i][0], cacc[i][1], cacc[i][2], cacc[i][3]);
        *(float4*)(g_ctx + (size_t)(b*SEQ + q0 + ty*4 + i) * D_MODEL + h*HDIM + tx*4) = v;
    }
}

/* ---------------- output projection: out = ctx @ Wo^T + bo ------------------ */
__global__ __launch_bounds__(256) void out_gemm(
    const float* __restrict__ Wo, const float* __restrict__ bo, float* __restrict__ Out)
{
    __shared__ float As[16][128];
    __shared__ float Bs[16][128];

    const int tid = threadIdx.x;
    const int ty  = tid >> 4, tx = tid & 15;
    const int m0  = blockIdx.y * 128;
    const int n0  = blockIdx.x * 128;
    const float* X = g_ctx;

    float acc[8][8];
    #pragma unroll
    for (int i = 0; i < 8; i++)
        #pragma unroll
        for (int j = 0; j < 8; j++) acc[i][j] = 0.f;

    for (int k0 = 0; k0 < 1024; k0 += 16) {
        __syncthreads();
        #pragma unroll
        for (int i = 0; i < 2; i++) {
            int f   = tid + i * 256;
            int row = f >> 2;
            int c4  = (f & 3) << 2;
            float4 a = *(const float4*)(X + (size_t)(m0 + row) * 1024 + k0 + c4);
            As[c4+0][row] = a.x; As[c4+1][row] = a.y; As[c4+2][row] = a.z; As[c4+3][row] = a.w;
            float4 b = *(const float4*)(Wo + (size_t)(n0 + row) * 1024 + k0 + c4);
            Bs[c4+0][row] = b.x; Bs[c4+1][row] = b.y; Bs[c4+2][row] = b.z; Bs[c4+3][row] = b.w;
        }
        __syncthreads();
        #pragma unroll
        for (int kk = 0; kk < 16; kk++) {
            float4 a0 = *(const float4*)&As[kk][ty*4];
            float4 a1 = *(const float4*)&As[kk][64 + ty*4];
            float4 b0 = *(const float4*)&Bs[kk][tx*4];
            float4 b1 = *(const float4*)&Bs[kk][64 + tx*4];
            float av[8] = {a0.x,a0.y,a0.z,a0.w,a1.x,a1.y,a1.z,a1.w};
            float bw[8] = {b0.x,b0.y,b0.z,b0.w,b1.x,b1.y,b1.z,b1.w};
            #pragma unroll
            for (int i = 0; i < 8; i++)
                #pragma unroll
                for (int j = 0; j < 8; j++)
                    acc[i][j] = fmaf(av[i], bw[j], acc[i][j]);
        }
    }

    #pragma unroll
    for (int ib = 0; ib < 2; ib++) {
        #pragma unroll
        for (int i = 0; i < 4; i++) {
            int r = m0 + ib*64 + ty*4 + i;
            #pragma unroll
            for (int jb = 0; jb < 2; jb++) {
                int c = n0 + jb*64 + tx*4;
                float4 v;
                v.x = acc[ib*4+i][jb*4+0] + bo[c+0];
                v.y = acc[ib*4+i][jb*4+1] + bo[c+1];
                v.z = acc[ib*4+i][jb*4+2] + bo[c+2];
                v.w = acc[ib*4+i][jb*4+3] + bo[c+3];
                *(float4*)(Out + (size_t)r * 1024 + c) = v;
            }
        }
    }
}

extern "C" void kernel_launch(void* const* d_in, const int* in_sizes, int n_in,
                              void* d_out, int out_size)
{
    const float* x  = (const float*)d_in[0];
    const float* Wq = (const float*)d_in[1];
    const float* bq = (const float*)d_in[2];
    const float* Wk = (const float*)d_in[3];
    const float* bk = (const float*)d_in[4];
    const float* Wv = (const float*)d_in[5];
    const float* bv = (const float*)d_in[6];
    const float* Wo = (const float*)d_in[7];
    const float* bo = (const float*)d_in[8];

    float* out  = (float*)d_out;                        /* (B,S,D) */
    float* attn = out + (size_t)MROWS * D_MODEL;        /* (B,H,S,S) */

    const int attn_smem = (4096 * 3 + 64 * 68) * 4;     /* 66560 bytes */
    cudaFuncSetAttribute(attn_kernel, cudaFuncAttributeMaxDynamicSharedMemorySize, attn_smem);

    dim3 gq(8, 32, 3);                /* N-tiles, M-tiles, {Q,K,V} */
    qkv_gemm<<<gq, 256>>>(x, Wq, Wk, Wv, bq, bk, bv);

    dim3 ga(NTILE, BATCH * NHEAD);    /* (32, 32) */
    attn_kernel<<<ga, 256, attn_smem>>>(attn);

    dim3 go(8, 32);
    out_gemm<<<go, 256>>>(Wo, bo, out);
}

// round 2
// speedup vs baseline: 3.1323x; 3.1323x over previous
#include <cuda_runtime.h>
#include <cstdint>
#include <math.h>

#define D_MODEL 1024
#define NHEAD   16
#define HDIM    64
#define SEQ     2048
#define BATCH   2
#define MROWS   (BATCH*SEQ)
#define ATT_SCALE 0.125f
#define NTILE   (SEQ/64)

/* scratch (device globals; allocation forbidden) */
__device__ float g_Q[BATCH*NHEAD*SEQ*HDIM];
__device__ float g_K[BATCH*NHEAD*SEQ*HDIM];
__device__ float g_V[BATCH*NHEAD*SEQ*HDIM];
__device__ float g_ctx[MROWS*D_MODEL];

/* ---------------- helpers ---------------- */
__device__ __forceinline__ uint32_t f2tf(float f) {
    uint32_t u; asm("cvt.rna.tf32.f32 %0, %1;" : "=r"(u) : "f"(f)); return u;
}
__device__ __forceinline__ uint32_t s2u(const void* p) {
    uint32_t a;
    asm("{ .reg .u64 t; cvta.to.shared.u64 t, %1; cvt.u32.u64 %0, t; }" : "=r"(a) : "l"(p));
    return a;
}
__device__ __forceinline__ void ldsm4(uint32_t& r0, uint32_t& r1, uint32_t& r2, uint32_t& r3, uint32_t addr) {
    asm volatile("ldmatrix.sync.aligned.m8n8.x4.shared.b16 {%0,%1,%2,%3}, [%4];"
                 : "=r"(r0), "=r"(r1), "=r"(r2), "=r"(r3) : "r"(addr));
}
__device__ __forceinline__ void mma_tf32(float* c, const uint32_t* a, uint32_t b0, uint32_t b1) {
    asm volatile(
        "mma.sync.aligned.m16n8k8.row.col.f32.tf32.tf32.f32 "
        "{%0,%1,%2,%3}, {%4,%5,%6,%7}, {%8,%9}, {%0,%1,%2,%3};"
        : "+f"(c[0]), "+f"(c[1]), "+f"(c[2]), "+f"(c[3])
        : "r"(a[0]), "r"(a[1]), "r"(a[2]), "r"(a[3]), "r"(b0), "r"(b1));
}

/* -------- shared GEMM mainloop: C(128x128) += X(128xK) * W(128xK)^T --------
   As/Bs: 128 rows x 8 chunks(16B) swizzled tf32 tiles.                      */
__device__ __forceinline__ void gemm_mainloop(
    const float* __restrict__ X, const float* __restrict__ W,
    int m0, int n0, uint32_t* As, uint32_t* Bs, float acc[4][4][4])
{
    const int tid = threadIdx.x, lane = tid & 31, wid = tid >> 5;
    const int wm = wid & 1, wn = wid >> 1;
    const uint32_t aBase = s2u(As), bBase = s2u(Bs);
    const int rsel = lane & 15, csel = lane >> 4;

    for (int k0 = 0; k0 < 1024; k0 += 32) {
        __syncthreads();
        #pragma unroll
        for (int i = 0; i < 4; i++) {
            int f = tid + i * 256;
            int row = f >> 3, ch = f & 7, sw = ch ^ (row & 7);
            float4 av = *(const float4*)(X + (size_t)(m0 + row) * 1024 + k0 + ch * 4);
            *(uint4*)&As[(row * 8 + sw) * 4] = make_uint4(f2tf(av.x), f2tf(av.y), f2tf(av.z), f2tf(av.w));
            float4 bv = *(const float4*)(W + (size_t)(n0 + row) * 1024 + k0 + ch * 4);
            *(uint4*)&Bs[(row * 8 + sw) * 4] = make_uint4(f2tf(bv.x), f2tf(bv.y), f2tf(bv.z), f2tf(bv.w));
        }
        __syncthreads();
        #pragma unroll
        for (int kk = 0; kk < 4; kk++) {
            uint32_t a[4][4];
            #pragma unroll
            for (int mf = 0; mf < 4; mf++) {
                int r = wm * 64 + mf * 16 + rsel;
                int c = kk * 2 + csel;
                ldsm4(a[mf][0], a[mf][1], a[mf][2], a[mf][3],
                      aBase + ((r * 8 + (c ^ (r & 7))) << 4));
            }
            uint32_t b[4][2];
            #pragma unroll
            for (int p = 0; p < 2; p++) {
                int r = wn * 32 + p * 16 + rsel;
                int c = kk * 2 + csel;
                uint32_t r0, r1, r2, r3;
                ldsm4(r0, r1, r2, r3, bBase + ((r * 8 + (c ^ (r & 7))) << 4));
                b[2*p][0] = r0; b[2*p+1][0] = r1; b[2*p][1] = r2; b[2*p+1][1] = r3;
            }
            #pragma unroll
            for (int mf = 0; mf < 4; mf++)
                #pragma unroll
                for (int nf = 0; nf < 4; nf++)
                    mma_tf32(acc[mf][nf], a[mf], b[nf][0], b[nf][1]);
        }
    }
}

/* ---------------- QKV projection (scatter to (B,H,S,Hd)) ---------------- */
__global__ __launch_bounds__(256, 2) void qkv_gemm(
    const float* __restrict__ X,
    const float* __restrict__ Wq, const float* __restrict__ Wk, const float* __restrict__ Wv,
    const float* __restrict__ bq, const float* __restrict__ bk, const float* __restrict__ bv)
{
    __shared__ uint32_t As[128 * 32];
    __shared__ uint32_t Bs[128 * 32];

    const float* W; const float* bias; float* Out;
    if (blockIdx.z == 0)      { W = Wq; bias = bq; Out = g_Q; }
    else if (blockIdx.z == 1) { W = Wk; bias = bk; Out = g_K; }
    else                      { W = Wv; bias = bv; Out = g_V; }

    const int m0 = blockIdx.y * 128, n0 = blockIdx.x * 128;
    float acc[4][4][4];
    #pragma unroll
    for (int i = 0; i < 4; i++) for (int j = 0; j < 4; j++) for (int k = 0; k < 4; k++) acc[i][j][k] = 0.f;

    gemm_mainloop(X, W, m0, n0, As, Bs, acc);

    const int tid = threadIdx.x, lane = tid & 31, wid = tid >> 5;
    const int wm = wid & 1, wn = wid >> 1;
    const int qr = lane >> 2, qc = (lane & 3) * 2;

    #pragma unroll
    for (int mf = 0; mf < 4; mf++) {
        int r0 = m0 + wm * 64 + mf * 16 + qr;
        int r1 = r0 + 8;
        #pragma unroll
        for (int nf = 0; nf < 4; nf++) {
            int col = n0 + wn * 32 + nf * 8 + qc;
            int head = col >> 6, hd = col & 63;
            float bx = bias[col], by = bias[col + 1];
            {
                int bb = r0 >> 11, s = r0 & 2047;
                float2 v = make_float2(acc[mf][nf][0] + bx, acc[mf][nf][1] + by);
                *(float2*)(Out + ((size_t)(bb * NHEAD + head) * SEQ + s) * HDIM + hd) = v;
            }
            {
                int bb = r1 >> 11, s = r1 & 2047;
                float2 v = make_float2(acc[mf][nf][2] + bx, acc[mf][nf][3] + by);
                *(float2*)(Out + ((size_t)(bb * NHEAD + head) * SEQ + s) * HDIM + hd) = v;
            }
        }
    }
}

/* ---------------- output projection (row-major) ---------------- */
__global__ __launch_bounds__(256, 2) void out_gemm(
    const float* __restrict__ Wo, const float* __restrict__ bo, float* __restrict__ Out)
{
    __shared__ uint32_t As[128 * 32];
    __shared__ uint32_t Bs[128 * 32];

    const int m0 = blockIdx.y * 128, n0 = blockIdx.x * 128;
    float acc[4][4][4];
    #pragma unroll
    for (int i = 0; i < 4; i++) for (int j = 0; j < 4; j++) for (int k = 0; k < 4; k++) acc[i][j][k] = 0.f;

    gemm_mainloop(g_ctx, Wo, m0, n0, As, Bs, acc);

    const int tid = threadIdx.x, lane = tid & 31, wid = tid >> 5;
    const int wm = wid & 1, wn = wid >> 1;
    const int qr = lane >> 2, qc = (lane & 3) * 2;

    #pragma unroll
    for (int mf = 0; mf < 4; mf++) {
        int r0 = m0 + wm * 64 + mf * 16 + qr;
        #pragma unroll
        for (int nf = 0; nf < 4; nf++) {
            int col = n0 + wn * 32 + nf * 8 + qc;
            float bx = bo[col], by = bo[col + 1];
            *(float2*)(Out + (size_t)r0 * 1024 + col) =
                make_float2(acc[mf][nf][0] + bx, acc[mf][nf][1] + by);
            *(float2*)(Out + (size_t)(r0 + 8) * 1024 + col) =
                make_float2(acc[mf][nf][2] + bx, acc[mf][nf][3] + by);
        }
    }
}

/* ---------------- attention: 128 q-rows/block, 64-key tiles, mma ---------------- */
#define QS_OFF 0
#define KS_OFF 8192
#define PS_OFF 12288
#define VS_OFF 20480
#define SMEM_U32 25088   /* 100352 bytes */

__global__ __launch_bounds__(256, 2) void attn_kernel(float* __restrict__ attn)
{
    extern __shared__ uint32_t sm[];
    uint32_t* Qs = sm + QS_OFF;       /* [128][16 chunks] tf32 swizzled */
    uint32_t* Ks = sm + KS_OFF;       /* [64][16 chunks]  tf32 swizzled */
    float*    Ps = (float*)(sm + PS_OFF);  /* [128][16 chunks] f32 swizzled */
    uint32_t* Vs = sm + VS_OFF;       /* [64][72] tf32, padded */

    const int qt = blockIdx.x, bh = blockIdx.y;
    const int q0 = qt * 128;
    const float* Qp = g_Q + (size_t)bh * SEQ * HDIM;
    const float* Kp = g_K + (size_t)bh * SEQ * HDIM;
    const float* Vp = g_V + (size_t)bh * SEQ * HDIM;
    float* attnP = attn + (size_t)bh * SEQ * SEQ;

    const int tid = threadIdx.x, lane = tid & 31, wid = tid >> 5;
    const int wrow = wid * 16;
    const int qr = lane >> 2, qc2 = (lane & 3) * 2;
    const int rsel = lane & 15, csel = lane >> 4;

    const uint32_t qBase = s2u(Qs), kBase = s2u(Ks), pBase = s2u(Ps);

    /* load Q tile */
    #pragma unroll
    for (int i = 0; i < 8; i++) {
        int f = tid + i * 256;
        int row = f >> 4, ch = f & 15;
        float4 v = *(const float4*)(Qp + (size_t)(q0 + row) * HDIM + ch * 4);
        *(uint4*)&Qs[(row * 16 + (ch ^ (row & 7))) * 4] =
            make_uint4(f2tf(v.x), f2tf(v.y), f2tf(v.z), f2tf(v.w));
    }

    const int rg0 = q0 + wrow + qr;
    const int rg1 = rg0 + 8;
    float mr0 = -INFINITY, mr1 = -INFINITY, lr0 = 0.f, lr1 = 0.f;
    const int kt_end = qt * 2 + 1;

    /* ---- pass 1: exact row max & sum ---- */
    for (int kt = 0; kt <= kt_end; kt++) {
        __syncthreads();
        #pragma unroll
        for (int i = 0; i < 4; i++) {
            int f = tid + i * 256;
            int row = f >> 4, ch = f & 15;
            float4 v = *(const float4*)(Kp + (size_t)(kt * 64 + row) * HDIM + ch * 4);
            *(uint4*)&Ks[(row * 16 + (ch ^ (row & 7))) * 4] =
                make_uint4(f2tf(v.x), f2tf(v.y), f2tf(v.z), f2tf(v.w));
        }
        __syncthreads();

        float S[8][4];
        #pragma unroll
        for (int nf = 0; nf < 8; nf++) { S[nf][0]=0.f; S[nf][1]=0.f; S[nf][2]=0.f; S[nf][3]=0.f; }

        #pragma unroll
        for (int kk = 0; kk < 8; kk++) {
            uint32_t a[4];
            { int r = wrow + rsel; int c = kk * 2 + csel;
              ldsm4(a[0], a[1], a[2], a[3], qBase + ((r * 16 + (c ^ (r & 7))) << 4)); }
            #pragma unroll
            for (int p = 0; p < 4; p++) {
                int r = p * 16 + rsel; int c = kk * 2 + csel;
                uint32_t b0, b1, b2, b3;
                ldsm4(b0, b1, b2, b3, kBase + ((r * 16 + (c ^ (r & 7))) << 4));
                mma_tf32(S[2*p],   a, b0, b2);
                mma_tf32(S[2*p+1], a, b1, b3);
            }
        }

        float tmax0 = -INFINITY, tmax1 = -INFINITY;
        #pragma unroll
        for (int nf = 0; nf < 8; nf++) {
            int c0 = kt * 64 + nf * 8 + qc2, c1 = c0 + 1;
            S[nf][0] = (c0 <= rg0) ? S[nf][0] * ATT_SCALE : -INFINITY;
            S[nf][1] = (c1 <= rg0) ? S[nf][1] * ATT_SCALE : -INFINITY;
            S[nf][2] = (c0 <= rg1) ? S[nf][2] * ATT_SCALE : -INFINITY;
            S[nf][3] = (c1 <= rg1) ? S[nf][3] * ATT_SCALE : -INFINITY;
            tmax0 = fmaxf(tmax0, fmaxf(S[nf][0], S[nf][1]));
            tmax1 = fmaxf(tmax1, fmaxf(S[nf][2], S[nf][3]));
        }
        tmax0 = fmaxf(tmax0, __shfl_xor_sync(0xffffffffu, tmax0, 1));
        tmax0 = fmaxf(tmax0, __shfl_xor_sync(0xffffffffu, tmax0, 2));
        tmax1 = fmaxf(tmax1, __shfl_xor_sync(0xffffffffu, tmax1, 1));
        tmax1 = fmaxf(tmax1, __shfl_xor_sync(0xffffffffu, tmax1, 2));
        float mn0 = fmaxf(mr0, tmax0), mn1 = fmaxf(mr1, tmax1);
        float s0 = 0.f, s1 = 0.f;
        #pragma unroll
        for (int nf = 0; nf < 8; nf++) {
            s0 += __expf(S[nf][0] - mn0) + __expf(S[nf][1] - mn0);
            s1 += __expf(S[nf][2] - mn1) + __expf(S[nf][3] - mn1);
        }
        s0 += __shfl_xor_sync(0xffffffffu, s0, 1);
        s0 += __shfl_xor_sync(0xffffffffu, s0, 2);
        s1 += __shfl_xor_sync(0xffffffffu, s1, 1);
        s1 += __shfl_xor_sync(0xffffffffu, s1, 2);
        lr0 = lr0 * __expf(mr0 - mn0) + s0; mr0 = mn0;
        lr1 = lr1 * __expf(mr1 - mn1) + s1; mr1 = mn1;
    }

    const float li0 = 1.0f / lr0, li1 = 1.0f / lr1;

    /* ---- pass 2: attn write + PV ---- */
    float C[8][4];
    #pragma unroll
    for (int nf = 0; nf < 8; nf++) { C[nf][0]=0.f; C[nf][1]=0.f; C[nf][2]=0.f; C[nf][3]=0.f; }

    for (int kt = 0; kt < NTILE; kt++) {
        if (kt <= kt_end) {
            __syncthreads();
            #pragma unroll
            for (int i = 0; i < 4; i++) {
                int f = tid + i * 256;
                int row = f >> 4, ch = f & 15;
                float4 v = *(const float4*)(Kp + (size_t)(kt * 64 + row) * HDIM + ch * 4);
                *(uint4*)&Ks[(row * 16 + (ch ^ (row & 7))) * 4] =
                    make_uint4(f2tf(v.x), f2tf(v.y), f2tf(v.z), f2tf(v.w));
                float4 w = *(const float4*)(Vp + (size_t)(kt * 64 + row) * HDIM + ch * 4);
                *(uint4*)&Vs[row * 72 + ch * 4] =
                    make_uint4(f2tf(w.x), f2tf(w.y), f2tf(w.z), f2tf(w.w));
            }
            __syncthreads();

            float S[8][4];
            #pragma unroll
            for (int nf = 0; nf < 8; nf++) { S[nf][0]=0.f; S[nf][1]=0.f; S[nf][2]=0.f; S[nf][3]=0.f; }

            #pragma unroll
            for (int kk = 0; kk < 8; kk++) {
                uint32_t a[4];
                { int r = wrow + rsel; int c = kk * 2 + csel;
                  ldsm4(a[0], a[1], a[2], a[3], qBase + ((r * 16 + (c ^ (r & 7))) << 4)); }
                #pragma unroll
                for (int p = 0; p < 4; p++) {
                    int r = p * 16 + rsel; int c = kk * 2 + csel;
                    uint32_t b0, b1, b2, b3;
                    ldsm4(b0, b1, b2, b3, kBase + ((r * 16 + (c ^ (r & 7))) << 4));
                    mma_tf32(S[2*p],   a, b0, b2);
                    mma_tf32(S[2*p+1], a, b1, b3);
                }
            }

            /* p values -> Ps (f32, swizzled) */
            const int rl0 = wrow + qr, rl1 = rl0 + 8;
            #pragma unroll
            for (int nf = 0; nf < 8; nf++) {
                int c0 = kt * 64 + nf * 8 + qc2, c1 = c0 + 1;
                float p00 = (c0 <= rg0) ? __expf(S[nf][0] * ATT_SCALE - mr0) * li0 : 0.f;
                float p01 = (c1 <= rg0) ? __expf(S[nf][1] * ATT_SCALE - mr0) * li0 : 0.f;
                float p10 = (c0 <= rg1) ? __expf(S[nf][2] * ATT_SCALE - mr1) * li1 : 0.f;
                float p11 = (c1 <= rg1) ? __expf(S[nf][3] * ATT_SCALE - mr1) * li1 : 0.f;
                int col = nf * 8 + qc2;
                int ch = col >> 2, off = col & 3;
                *(float2*)&Ps[(rl0 * 16 + (ch ^ (rl0 & 7))) * 4 + off] = make_float2(p00, p01);
                *(float2*)&Ps[(rl1 * 16 + (ch ^ (rl1 & 7))) * 4 + off] = make_float2(p10, p11);
            }
            __syncthreads();

            /* coalesced attn write from Ps */
            #pragma unroll
            for (int i = 0; i < 8; i++) {
                int f = tid + i * 256;
                int row = f >> 4, ch = f & 15;
                float4 v = *(float4*)&Ps[(row * 16 + (ch ^ (row & 7))) * 4];
                *(float4*)(attnP + (size_t)(q0 + row) * SEQ + kt * 64 + ch * 4) = v;
            }

            /* PV: C += P * V */
            #pragma unroll
            for (int kk = 0; kk < 8; kk++) {
                uint32_t a[4];
                { int r = wrow + rsel; int c = kk * 2 + csel;
                  ldsm4(a[0], a[1], a[2], a[3], pBase + ((r * 16 + (c ^ (r & 7))) << 4)); }
                a[0] = f2tf(__uint_as_float(a[0]));
                a[1] = f2tf(__uint_as_float(a[1]));
                a[2] = f2tf(__uint_as_float(a[2]));
                a[3] = f2tf(__uint_as_float(a[3]));
                #pragma unroll
                for (int nf = 0; nf < 8; nf++) {
                    uint32_t b0 = Vs[(kk * 8 + (lane & 3)) * 72 + nf * 8 + (lane >> 2)];
                    uint32_t b1 = Vs[(kk * 8 + (lane & 3) + 4) * 72 + nf * 8 + (lane >> 2)];
                    mma_tf32(C[nf], a, b0, b1);
                }
            }
        } else {
            float4 z = make_float4(0.f, 0.f, 0.f, 0.f);
            #pragma unroll
            for (int i = 0; i < 8; i++) {
                int f = tid + i * 256;
                int row = f >> 4, ch = f & 15;
                *(float4*)(attnP + (size_t)(q0 + row) * SEQ + kt * 64 + ch * 4) = z;
            }
        }
    }

    /* ctx -> (B,S,D) row-major */
    const int b = bh >> 4, h = bh & 15;
    #pragma unroll
    for (int nf = 0; nf < 8; nf++) {
        int col = h * HDIM + nf * 8 + qc2;
        *(float2*)(g_ctx + (size_t)(b * SEQ + rg0) * D_MODEL + col) = make_float2(C[nf][0], C[nf][1]);
        *(float2*)(g_ctx + (size_t)(b * SEQ + rg1) * D_MODEL + col) = make_float2(C[nf][2], C[nf][3]);
    }
}

extern "C" void kernel_launch(void* const* d_in, const int* in_sizes, int n_in,
                              void* d_out, int out_size)
{
    const float* x  = (const float*)d_in[0];
    const float* Wq = (const float*)d_in[1];
    const float* bq = (const float*)d_in[2];
    const float* Wk = (const float*)d_in[3];
    const float* bk = (const float*)d_in[4];
    const float* Wv = (const float*)d_in[5];
    const float* bv = (const float*)d_in[6];
    const float* Wo = (const float*)d_in[7];
    const float* bo = (const float*)d_in[8];

    float* out  = (float*)d_out;
    float* attn = out + (size_t)MROWS * D_MODEL;

    const int attn_smem = SMEM_U32 * 4;   /* 100352 bytes */
    cudaFuncSetAttribute(attn_kernel, cudaFuncAttributeMaxDynamicSharedMemorySize, attn_smem);

    qkv_gemm<<<dim3(8, 32, 3), 256>>>(x, Wq, Wk, Wv, bq, bk, bv);
    attn_kernel<<<dim3(SEQ / 128, BATCH * NHEAD), 256, attn_smem>>>(attn);
    out_gemm<<<dim3(8, 32), 256>>>(Wo, bo, out);
}